// round 8
// baseline (speedup 1.0000x reference)
#include <cuda_runtime.h>

#define TT 512
typedef unsigned long long ull;

// ---------- packed f32x2 helpers ----------
__device__ __forceinline__ ull pk2(float a, float b) {
    ull r; asm("mov.b64 %0, {%1,%2};" : "=l"(r) : "f"(a), "f"(b)); return r;
}
__device__ __forceinline__ float sum2(ull v) {
    float a, b; asm("mov.b64 {%0,%1}, %2;" : "=f"(a), "=f"(b) : "l"(v));
    return a + b;
}
__device__ __forceinline__ ull fma2(ull a, ull b, ull c) {
    ull d; asm("fma.rn.f32x2 %0, %1, %2, %3;" : "=l"(d) : "l"(a), "l"(b), "l"(c));
    return d;
}
__device__ __forceinline__ ull add2(ull a, ull b) {
    ull d; asm("add.rn.f32x2 %0, %1, %2;" : "=l"(d) : "l"(a), "l"(b));
    return d;
}

// ---------- activations (EX2+RCP; validated rel_err ~2e-7 over full recurrence) ----------
__device__ __forceinline__ float rcpf_(float x) {
    float r; asm("rcp.approx.f32 %0, %1;" : "=f"(r) : "f"(x)); return r;
}
__device__ __forceinline__ float ex2f_(float x) {
    float r; asm("ex2.approx.f32 %0, %1;" : "=f"(r) : "f"(x)); return r;
}
__device__ __forceinline__ float tanh_(float x) {
    float e = ex2f_(2.8853900817779268f * x);
    return 1.0f - 2.0f * rcpf_(e + 1.0f);
}
#define L2E 1.4426950408889634f

// load 16 floats (64B, 16B-aligned smem row) as 8 packed f32x2
__device__ __forceinline__ void ld8u(ull* v, const float* p) {
    const ulonglong2* q = (const ulonglong2*)p;
    ulonglong2 a = q[0], b = q[1], c = q[2], d = q[3];
    v[0]=a.x; v[1]=a.y; v[2]=b.x; v[3]=b.y; v[4]=c.x; v[5]=c.y; v[6]=d.x; v[7]=d.y;
}

// One LSTM cell eval for ONE batch element, whole warp cooperating.
// Lane j holds gate rows {j, j+32} in registers (rows: i=0..15 f=16..31
// g=32..47 o=48..63 -> lane u<16: (i_u, g_u); lane u+16: (f_u, o_u)).
// NOTE: no __restrict__ on rows — dst may alias recrow (single-buffered h);
// per-thread program order (all LDS before the STS) keeps this correct.
__device__ __forceinline__ void task1(
    const ull* __restrict__ wv, ull bi0, ull bi1,
    const float* inrow, const float* recrow,
    float& c, float* dst,
    float k1, float actm, float actb, bool lo, int lane)
{
    ull v0[8], v1[8];
    ld8u(v0, inrow);
    ld8u(v1, recrow);
    ull a0 = bi0, a1 = bi1, a0b = 0ULL, a1b = 0ULL;   // 4 independent 8-deep chains
#pragma unroll
    for (int kk = 0; kk < 8; ++kk) {
        a0  = fma2(wv[kk],      v0[kk], a0);
        a1  = fma2(wv[16 + kk], v0[kk], a1);
        a0b = fma2(wv[8 + kk],  v1[kk], a0b);
        a1b = fma2(wv[24 + kk], v1[kk], a1b);
    }
    float s0 = sum2(add2(a0, a0b));
    float s1 = sum2(add2(a1, a1b));
    float act0 = rcpf_(1.0f + ex2f_(-L2E * s0));                 // sigmoid
    float act1 = fmaf(actm, rcpf_(1.0f + ex2f_(k1 * s1)), actb); // tanh or sigm
    float p0 = __shfl_xor_sync(0xffffffffu, act0, 16);
    float p1 = __shfl_xor_sync(0xffffffffu, act1, 16);
    float fv = lo ? p0 : act0;
    float iv = lo ? act0 : p0;
    float gv = lo ? act1 : p1;
    float ov = lo ? p1 : act1;
    c = fmaf(fv, c, iv * gv);
    float h = ov * tanh_(c);
    if (lo) dst[lane] = h;
}

// CTA: 256 threads = 8 warps; 32 elems; grid 128.
// Warp w owns elems 4w..4w+3 for BOTH layers: zero cross-warp dependencies,
// zero block barriers in the main loop (only __syncwarp). Both layers' weights
// live in registers (128 regs of weights; 256-reg budget at 256 thr/CTA).
__global__ void __launch_bounds__(256, 1) lstm_auto(
    const float* __restrict__ x,
    const float* __restrict__ Wih0, const float* __restrict__ Whh0,
    const float* __restrict__ bih0, const float* __restrict__ bhh0,
    const float* __restrict__ Wih1, const float* __restrict__ Whh1,
    const float* __restrict__ bih1, const float* __restrict__ bhh1,
    const float* __restrict__ Wproj, const float* __restrict__ bproj,
    const float* __restrict__ gamma, const float* __restrict__ beta,
    float* __restrict__ out)
{
    __shared__ __align__(16) float h0r[8][4][16];    // [warp][elem][unit] single-buffer
    __shared__ __align__(16) float h1r[8][4][16];
    __shared__ __align__(16) float4 xs4[8][2][16];   // [warp][parity][e*4+q]

    const int tid  = threadIdx.x;
    const int w    = tid >> 5;
    const int lane = tid & 31;
    const bool lo  = (lane < 16);
    const int elem0 = blockIdx.x * 32 + w * 4;

    // ---- both layers' weights into registers: lane -> rows {lane, lane+32} ----
    ull w0[32], w1[32];
    ull b00, b01, b10, b11;
    {
        int rA = lane, rB = lane + 32;
#pragma unroll
        for (int kk = 0; kk < 8; ++kk) {
            w0[kk]      = pk2(Wih0[rA * 16 + 2 * kk], Wih0[rA * 16 + 2 * kk + 1]);
            w0[8 + kk]  = pk2(Whh0[rA * 16 + 2 * kk], Whh0[rA * 16 + 2 * kk + 1]);
            w0[16 + kk] = pk2(Wih0[rB * 16 + 2 * kk], Wih0[rB * 16 + 2 * kk + 1]);
            w0[24 + kk] = pk2(Whh0[rB * 16 + 2 * kk], Whh0[rB * 16 + 2 * kk + 1]);
            w1[kk]      = pk2(Wih1[rA * 16 + 2 * kk], Wih1[rA * 16 + 2 * kk + 1]);
            w1[8 + kk]  = pk2(Whh1[rA * 16 + 2 * kk], Whh1[rA * 16 + 2 * kk + 1]);
            w1[16 + kk] = pk2(Wih1[rB * 16 + 2 * kk], Wih1[rB * 16 + 2 * kk + 1]);
            w1[24 + kk] = pk2(Whh1[rB * 16 + 2 * kk], Whh1[rB * 16 + 2 * kk + 1]);
        }
        b00 = pk2(bih0[rA] + bhh0[rA], 0.f);
        b01 = pk2(bih0[rB] + bhh0[rB], 0.f);
        b10 = pk2(bih1[rA] + bhh1[rA], 0.f);
        b11 = pk2(bih1[rB] + bhh1[rB], 0.f);
    }
    const float actm = lo ? 2.0f : 1.0f;
    const float actb = lo ? -1.0f : 0.0f;
    const float k1   = -L2E * actm;

    // zero this warp's h rows (warp-local)
    if (lo) {
#pragma unroll
        for (int e = 0; e < 4; ++e) { h0r[w][e][lane] = 0.f; h1r[w][e][lane] = 0.f; }
    }

    // ---- warp-private x staging: lane<16 -> (elem e=lane>>2, quad q=lane&3) ----
    const float4* xq = (const float4*)x;
    float4 xn;
    if (lo) {
        int e = lane >> 2, q = lane & 3;
        xq = (const float4*)(x + ((size_t)(elem0 + e) * TT) * 16) + q;
        xs4[w][0][lane] = xq[0];      // x[0]
        xn = xq[4];                   // x[1]
    }
    __syncwarp();

    float c0[4] = {0.f, 0.f, 0.f, 0.f};
    float c1[4] = {0.f, 0.f, 0.f, 0.f};

    const float* xrow0 = (const float*)&xs4[w][0][0];
    const float* xrow1 = (const float*)&xs4[w][1][0];

#pragma unroll 1
    for (int t = 0; t < TT; ++t) {
        const int par = t & 1;
        // publish x[t+1] into the other parity buffer; prefetch x[t+2]
        if (lo) {
            if (par == 0) xs4[w][1][lane] = xn; else xs4[w][0][lane] = xn;
            int tf = t + 2 < TT ? t + 2 : TT - 1;
            xn = xq[(size_t)tf * 4];
        }
        const float* xr = par ? xrow1 : xrow0;
        // ---- layer 0: 4 independent tasks (single-buffered h0) ----
#pragma unroll
        for (int e = 0; e < 4; ++e)
            task1(w0, b00, b01, xr + 16 * e, &h0r[w][e][0],
                  c0[e], &h0r[w][e][0], k1, actm, actb, lo, lane);
        __syncwarp();
        // ---- layer 1: input = fresh h0, recurrent = h1 ----
#pragma unroll
        for (int e = 0; e < 4; ++e)
            task1(w1, b10, b11, &h0r[w][e][0], &h1r[w][e][0],
                  c1[e], &h1r[w][e][0], k1, actm, actb, lo, lane);
        __syncwarp();
    }

    // ---- projection + LayerNorm + tanh (warp-local: lanes 0-3, one elem each) ----
    if (lane < 4) {
        const int e = lane;
        float hv[16];
#pragma unroll
        for (int k = 0; k < 16; ++k) hv[k] = h1r[w][e][k];
        float z[16];
        float mu = 0.f;
#pragma unroll
        for (int j = 0; j < 16; ++j) {
            float s = bproj[j];
#pragma unroll
            for (int k = 0; k < 16; ++k) s = fmaf(Wproj[j * 16 + k], hv[k], s);
            z[j] = s;
            mu += s;
        }
        mu *= (1.0f / 16.0f);
        float var = 0.f;
#pragma unroll
        for (int j = 0; j < 16; ++j) { float d = z[j] - mu; var = fmaf(d, d, var); }
        var *= (1.0f / 16.0f);
        float rs = rsqrtf(var + 1e-5f);
#pragma unroll
        for (int j = 0; j < 16; ++j) {
            float zn = (z[j] - mu) * rs * gamma[j] + beta[j];
            out[(size_t)(elem0 + e) * 16 + j] = tanh_(zn);
        }
    }
}

extern "C" void kernel_launch(void* const* d_in, const int* in_sizes, int n_in,
                              void* d_out, int out_size) {
    const float* x     = (const float*)d_in[0];
    const float* Wih0  = (const float*)d_in[1];
    const float* Whh0  = (const float*)d_in[2];
    const float* bih0  = (const float*)d_in[3];
    const float* bhh0  = (const float*)d_in[4];
    const float* Wih1  = (const float*)d_in[5];
    const float* Whh1  = (const float*)d_in[6];
    const float* bih1  = (const float*)d_in[7];
    const float* bhh1  = (const float*)d_in[8];
    const float* Wproj = (const float*)d_in[9];
    const float* bproj = (const float*)d_in[10];
    const float* gamma = (const float*)d_in[11];
    const float* beta  = (const float*)d_in[12];
    float* out = (float*)d_out;

    int B = in_sizes[0] / (TT * 16);   // 4096
    int grid = B / 32;                 // 128 CTAs, 32 elems each

    lstm_auto<<<grid, 256>>>(x, Wih0, Whh0, bih0, bhh0,
                             Wih1, Whh1, bih1, bhh1,
                             Wproj, bproj, gamma, beta, out);
}

// round 9
// speedup vs baseline: 2.0285x; 2.0285x over previous
#include <cuda_runtime.h>

#define TT 512
typedef unsigned long long ull;

// ---------- packed f32x2 helpers ----------
__device__ __forceinline__ ull pk2(float a, float b) {
    ull r; asm("mov.b64 %0, {%1,%2};" : "=l"(r) : "f"(a), "f"(b)); return r;
}
__device__ __forceinline__ float sum2(ull v) {
    float a, b; asm("mov.b64 {%0,%1}, %2;" : "=f"(a), "=f"(b) : "l"(v));
    return a + b;
}
__device__ __forceinline__ ull fma2(ull a, ull b, ull c) {
    ull d; asm("fma.rn.f32x2 %0, %1, %2, %3;" : "=l"(d) : "l"(a), "l"(b), "l"(c));
    return d;
}

// ---------- activations ----------
// fast path (recurrence): native MUFU tanh, err ~2^-11
__device__ __forceinline__ float tanhap_(float x) {
    float r; asm("tanh.approx.f32 %0, %1;" : "=f"(r) : "f"(x)); return r;
}
// accurate path (epilogue only): EX2+RCP
__device__ __forceinline__ float rcpf_(float x) {
    float r; asm("rcp.approx.f32 %0, %1;" : "=f"(r) : "f"(x)); return r;
}
__device__ __forceinline__ float ex2f_(float x) {
    float r; asm("ex2.approx.f32 %0, %1;" : "=f"(r) : "f"(x)); return r;
}
__device__ __forceinline__ float tanh_(float x) {
    float e = ex2f_(2.8853900817779268f * x);
    return 1.0f - 2.0f * rcpf_(e + 1.0f);
}

// pairwise named barrier: warps w and w+8 share id (w&7)+1, 64 threads
#define PBAR(id) asm volatile("bar.sync %0, %1;" :: "r"(id), "r"(64) : "memory")

// load 16 floats (64B, 16B-aligned smem row) as 8 packed f32x2
__device__ __forceinline__ void ld8u(ull* v, const float* p) {
    const ulonglong2* q = (const ulonglong2*)p;
    ulonglong2 a = q[0], b = q[1], c = q[2], d = q[3];
    v[0]=a.x; v[1]=a.y; v[2]=b.x; v[3]=b.y; v[4]=c.x; v[5]=c.y; v[6]=d.x; v[7]=d.y;
}

// One LSTM cell eval for ONE batch element, whole warp cooperating.
// Lane j holds gate rows {j, j+32} in registers (rows: i=0..15 f=16..31
// g=32..47 o=48..63 -> lane u<16: (i_u, g_u); lane u+16: (f_u, o_u)).
// km/am/ab implement act1 = tanh(s1) (lanes<16) or sigmoid(s1) (lanes>=16)
// uniformly as fma(am, tanh(km*s1), ab).
__device__ __forceinline__ void task1(
    const ull* __restrict__ wv, ull bi0, ull bi1,
    const float* __restrict__ inrow, const float* __restrict__ recrow,
    float& c, float* __restrict__ dst,
    float km, float am, float ab, bool lo, int lane)
{
    ull v0[8], v1[8];
    ld8u(v0, inrow);
    ld8u(v1, recrow);
    ull a0 = bi0, a1 = bi1;            // 2 chains of 16
#pragma unroll
    for (int kk = 0; kk < 8; ++kk) {
        a0 = fma2(wv[kk],      v0[kk], a0);
        a1 = fma2(wv[16 + kk], v0[kk], a1);
    }
#pragma unroll
    for (int kk = 0; kk < 8; ++kk) {
        a0 = fma2(wv[8 + kk],  v1[kk], a0);
        a1 = fma2(wv[24 + kk], v1[kk], a1);
    }
    float s0 = sum2(a0);
    float s1 = sum2(a1);
    float act0 = fmaf(0.5f, tanhap_(0.5f * s0), 0.5f);   // sigmoid
    float act1 = fmaf(am, tanhap_(km * s1), ab);         // tanh or sigmoid
    float p0 = __shfl_xor_sync(0xffffffffu, act0, 16);
    float p1 = __shfl_xor_sync(0xffffffffu, act1, 16);
    float fv = lo ? p0 : act0;
    float iv = lo ? act0 : p0;
    float gv = lo ? act1 : p1;
    float ov = lo ? p1 : act1;
    c = fmaf(fv, c, iv * gv);
    float h = ov * tanhap_(c);
    if (lo) dst[lane] = h;
}

__device__ __forceinline__ void cell4(
    const ull* __restrict__ wv, ull bi0, ull bi1,
    const float* __restrict__ inb, const float* __restrict__ recb,
    float* __restrict__ c, float* __restrict__ dstb,
    float km, float am, float ab, bool lo, int lane)
{
#pragma unroll
    for (int e = 0; e < 4; ++e)
        task1(wv, bi0, bi1, inb + 16 * e, recb + 16 * e,
              c[e], dstb + 16 * e, km, am, ab, lo, lane);
}

// CTA: 512 threads = 16 warps; 32 elems; grid 128. (R7 structure.)
// Warps 0-7: layer 0 ("A"), elems 4w..4w+3. Warps 8-15: layer 1 ("B"),
// one step behind. A-warp w <-> B-warp w+8 sync via named barrier, 64 thr.
__global__ void __launch_bounds__(512, 1) lstm_pair2(
    const float* __restrict__ x,
    const float* __restrict__ Wih0, const float* __restrict__ Whh0,
    const float* __restrict__ bih0, const float* __restrict__ bhh0,
    const float* __restrict__ Wih1, const float* __restrict__ Whh1,
    const float* __restrict__ bih1, const float* __restrict__ bhh1,
    const float* __restrict__ Wproj, const float* __restrict__ bproj,
    const float* __restrict__ gamma, const float* __restrict__ beta,
    float* __restrict__ out)
{
    __shared__ __align__(16) float h0b[2][32][16];   // [parity][elem][unit]
    __shared__ __align__(16) float h1b[2][32][16];
    __shared__ __align__(16) float4 xs4[2][8][16];   // [parity][A-warp][e*4+q]

    const int tid = threadIdx.x;
    const int w    = tid >> 5;
    const int lane = tid & 31;
    const bool isA = (w < 8);
    const bool lo  = (lane < 16);
    const int wp   = w & 7;
    const int ebase = wp * 4;
    const int elem0 = blockIdx.x * 32;
    const int bid = wp + 1;

    // ---- weights into registers: lane -> gate rows {lane, lane+32} ----
    ull wv[32];
    ull bi0, bi1;
    {
        const float* Wi = isA ? Wih0 : Wih1;
        const float* Wh = isA ? Whh0 : Whh1;
        const float* bi = isA ? bih0 : bih1;
        const float* bh = isA ? bhh0 : bhh1;
        int rA = lane, rB = lane + 32;
#pragma unroll
        for (int kk = 0; kk < 8; ++kk) {
            wv[kk]      = pk2(Wi[rA * 16 + 2 * kk], Wi[rA * 16 + 2 * kk + 1]);
            wv[8 + kk]  = pk2(Wh[rA * 16 + 2 * kk], Wh[rA * 16 + 2 * kk + 1]);
            wv[16 + kk] = pk2(Wi[rB * 16 + 2 * kk], Wi[rB * 16 + 2 * kk + 1]);
            wv[24 + kk] = pk2(Wh[rB * 16 + 2 * kk], Wh[rB * 16 + 2 * kk + 1]);
        }
        bi0 = pk2(bi[rA] + bh[rA], 0.f);
        bi1 = pk2(bi[rB] + bh[rB], 0.f);
    }
    // act1 selector: lanes<16 -> tanh (km=1,am=1,ab=0); else sigmoid (0.5,0.5,0.5)
    const float km = lo ? 1.0f : 0.5f;
    const float am = lo ? 1.0f : 0.5f;
    const float ab = lo ? 0.0f : 0.5f;

    for (int idx = tid; idx < 1024; idx += 512) {
        ((float*)h0b)[idx] = 0.f;
        ((float*)h1b)[idx] = 0.f;
    }

    // ---- warp-private x staging (A warps, lanes 0-15) ----
    const float4* xq = (const float4*)x;
    float4 xnA, xnB;
    if (isA) {
        int e = lane >> 2, q = lane & 3;
        xq = (const float4*)(x + ((size_t)(elem0 + ebase + e) * TT) * 16) + q;
        if (lo) {
            xs4[0][wp][lane] = xq[0];   // x[0]
            xnB = xq[4];                // x[1]
        }
    }

    float c[4] = {0.f, 0.f, 0.f, 0.f};

    const float* inS1  = isA ? (const float*)&xs4[0][wp][0] : &h0b[1][ebase][0];
    const float* recS1 = isA ? &h0b[1][ebase][0] : &h1b[0][ebase][0];
    float*       dstS1 = isA ? &h0b[0][ebase][0] : &h1b[1][ebase][0];
    const float* inS2  = isA ? (const float*)&xs4[1][wp][0] : &h0b[0][ebase][0];
    const float* recS2 = isA ? &h0b[0][ebase][0] : &h1b[1][ebase][0];
    float*       dstS2 = isA ? &h0b[1][ebase][0] : &h1b[0][ebase][0];

    __syncthreads();

#pragma unroll 1
    for (int t0 = 0; t0 < TT; t0 += 2) {
        // ===== S1: global step t0 =====
        if (isA) {
            if (lo) {
                xs4[1][wp][lane] = xnB;
                int tf = t0 + 2 < TT ? t0 + 2 : TT - 1;
                xnA = xq[(size_t)tf * 4];
            }
            cell4(wv, bi0, bi1, inS1, recS1, c, dstS1, km, am, ab, lo, lane);
        } else if (t0 > 0) {
            cell4(wv, bi0, bi1, inS1, recS1, c, dstS1, km, am, ab, lo, lane);
        }
        PBAR(bid);
        // ===== S2: global step t0+1 =====
        if (isA && lo) {
            xs4[0][wp][lane] = xnA;
            int tf = t0 + 3 < TT ? t0 + 3 : TT - 1;
            xnB = xq[(size_t)tf * 4];
        }
        cell4(wv, bi0, bi1, inS2, recS2, c, dstS2, km, am, ab, lo, lane);
        PBAR(bid);
    }

    // ---- tail: B computes h1[TT-1] ----
    if (!isA)
        cell4(wv, bi0, bi1, inS1, recS1, c, dstS1, km, am, ab, lo, lane);
    __syncthreads();

    // ---- projection + LayerNorm + tanh (warp 0; accurate tanh) ----
    if (w == 0) {
        float hv[16];
#pragma unroll
        for (int k = 0; k < 16; ++k) hv[k] = h1b[1][lane][k];
        float z[16];
        float mu = 0.f;
#pragma unroll
        for (int j = 0; j < 16; ++j) {
            float s = bproj[j];
#pragma unroll
            for (int k = 0; k < 16; ++k) s = fmaf(Wproj[j * 16 + k], hv[k], s);
            z[j] = s;
            mu += s;
        }
        mu *= (1.0f / 16.0f);
        float var = 0.f;
#pragma unroll
        for (int j = 0; j < 16; ++j) { float d = z[j] - mu; var = fmaf(d, d, var); }
        var *= (1.0f / 16.0f);
        float rs = rsqrtf(var + 1e-5f);
#pragma unroll
        for (int j = 0; j < 16; ++j) {
            float zn = (z[j] - mu) * rs * gamma[j] + beta[j];
            out[(size_t)(elem0 + lane) * 16 + j] = tanh_(zn);
        }
    }
}

extern "C" void kernel_launch(void* const* d_in, const int* in_sizes, int n_in,
                              void* d_out, int out_size) {
    const float* x     = (const float*)d_in[0];
    const float* Wih0  = (const float*)d_in[1];
    const float* Whh0  = (const float*)d_in[2];
    const float* bih0  = (const float*)d_in[3];
    const float* bhh0  = (const float*)d_in[4];
    const float* Wih1  = (const float*)d_in[5];
    const float* Whh1  = (const float*)d_in[6];
    const float* bih1  = (const float*)d_in[7];
    const float* bhh1  = (const float*)d_in[8];
    const float* Wproj = (const float*)d_in[9];
    const float* bproj = (const float*)d_in[10];
    const float* gamma = (const float*)d_in[11];
    const float* beta  = (const float*)d_in[12];
    float* out = (float*)d_out;

    int B = in_sizes[0] / (TT * 16);   // 4096
    int grid = B / 32;                 // 128 CTAs

    lstm_pair2<<<grid, 512>>>(x, Wih0, Whh0, bih0, bhh0,
                              Wih1, Whh1, bih1, bhh1,
                              Wproj, bproj, gamma, beta, out);
}